// round 1
// baseline (speedup 1.0000x reference)
#include <cuda_runtime.h>

// TwoRobots Euler step — algebraically simplified (trig identities collapse
// Fk*cos(atan2(dy,dx)) -> KS*dx etc.), making the update affine per column.
// Pure streaming kernel: 112 MB traffic, HBM-bound. float4 vectorized.

#define HSTEP 0.05f
#define KS    2.0f
#define CD    2.0f

__global__ __launch_bounds__(256)
void tworobots_step(const float4* __restrict__ x,
                    const float4* __restrict__ u,
                    const float4* __restrict__ w,
                    const float*  __restrict__ xbar,
                    float4* __restrict__ out,
                    int n4)
{
    int i = blockIdx.x * blockDim.x + threadIdx.x;
    if (i >= n4) return;

    const float xb0 = __ldg(&xbar[0]);
    const float xb1 = __ldg(&xbar[1]);
    const float xb4 = __ldg(&xbar[4]);
    const float xb5 = __ldg(&xbar[5]);

    // Row-major [8, B]: row r starts at r*n4 (in float4 units).
    float4 x0 = x[0 * n4 + i];
    float4 x1 = x[1 * n4 + i];
    float4 x2 = x[2 * n4 + i];
    float4 x3 = x[3 * n4 + i];
    float4 x4 = x[4 * n4 + i];
    float4 x5 = x[5 * n4 + i];
    float4 x6 = x[6 * n4 + i];
    float4 x7 = x[7 * n4 + i];

    float4 u0 = u[0 * n4 + i];
    float4 u1 = u[1 * n4 + i];
    float4 u2 = u[2 * n4 + i];
    float4 u3 = u[3 * n4 + i];

    float4 w0 = w[0 * n4 + i];
    float4 w1 = w[1 * n4 + i];
    float4 w2 = w[2 * n4 + i];
    float4 w3 = w[3 * n4 + i];
    float4 w4 = w[4 * n4 + i];
    float4 w5 = w[5 * n4 + i];
    float4 w6 = w[6 * n4 + i];
    float4 w7 = w[7 * n4 + i];

    float4 o0, o1, o2, o3, o4, o5, o6, o7;

#define LANE(c)                                                              \
    {                                                                        \
        /* agent 1 */                                                        \
        float fgx1 = fmaf(-KS, (x0.c - xb0), -CD * x2.c);                    \
        float fgy1 = fmaf(-KS, (x1.c - xb1), -CD * x3.c);                    \
        o0.c = fmaf(HSTEP, x2.c, x0.c) + w0.c;                               \
        o1.c = fmaf(HSTEP, x3.c, x1.c) + w1.c;                               \
        o2.c = fmaf(HSTEP, (fgx1 + u0.c), x2.c) + w2.c;                      \
        o3.c = fmaf(HSTEP, (fgy1 + u1.c), x3.c) + w3.c;                      \
        /* agent 2 */                                                        \
        float fgx2 = fmaf(-KS, (x4.c - xb4), -CD * x6.c);                    \
        float fgy2 = fmaf(-KS, (x5.c - xb5), -CD * x7.c);                    \
        o4.c = fmaf(HSTEP, x6.c, x4.c) + w4.c;                               \
        o5.c = fmaf(HSTEP, x7.c, x5.c) + w5.c;                               \
        o6.c = fmaf(HSTEP, (fgx2 + u2.c), x6.c) + w6.c;                      \
        o7.c = fmaf(HSTEP, (fgy2 + u3.c), x7.c) + w7.c;                      \
    }

    LANE(x)
    LANE(y)
    LANE(z)
    LANE(w)
#undef LANE

    out[0 * n4 + i] = o0;
    out[1 * n4 + i] = o1;
    out[2 * n4 + i] = o2;
    out[3 * n4 + i] = o3;
    out[4 * n4 + i] = o4;
    out[5 * n4 + i] = o5;
    out[6 * n4 + i] = o6;
    out[7 * n4 + i] = o7;
}

// Scalar fallback for B not divisible by 4 (not expected here, but safe).
__global__ __launch_bounds__(256)
void tworobots_step_scalar(const float* __restrict__ x,
                           const float* __restrict__ u,
                           const float* __restrict__ w,
                           const float* __restrict__ xbar,
                           float* __restrict__ out,
                           int B)
{
    int i = blockIdx.x * blockDim.x + threadIdx.x;
    if (i >= B) return;

    const float xb0 = __ldg(&xbar[0]);
    const float xb1 = __ldg(&xbar[1]);
    const float xb4 = __ldg(&xbar[4]);
    const float xb5 = __ldg(&xbar[5]);

    float x0 = x[0 * B + i], x1 = x[1 * B + i], x2 = x[2 * B + i], x3 = x[3 * B + i];
    float x4 = x[4 * B + i], x5 = x[5 * B + i], x6 = x[6 * B + i], x7 = x[7 * B + i];
    float u0 = u[0 * B + i], u1 = u[1 * B + i], u2 = u[2 * B + i], u3 = u[3 * B + i];

    float fgx1 = fmaf(-KS, (x0 - xb0), -CD * x2);
    float fgy1 = fmaf(-KS, (x1 - xb1), -CD * x3);
    float fgx2 = fmaf(-KS, (x4 - xb4), -CD * x6);
    float fgy2 = fmaf(-KS, (x5 - xb5), -CD * x7);

    out[0 * B + i] = fmaf(HSTEP, x2, x0) + w[0 * B + i];
    out[1 * B + i] = fmaf(HSTEP, x3, x1) + w[1 * B + i];
    out[2 * B + i] = fmaf(HSTEP, (fgx1 + u0), x2) + w[2 * B + i];
    out[3 * B + i] = fmaf(HSTEP, (fgy1 + u1), x3) + w[3 * B + i];
    out[4 * B + i] = fmaf(HSTEP, x6, x4) + w[4 * B + i];
    out[5 * B + i] = fmaf(HSTEP, x7, x5) + w[5 * B + i];
    out[6 * B + i] = fmaf(HSTEP, (fgx2 + u2), x6) + w[6 * B + i];
    out[7 * B + i] = fmaf(HSTEP, (fgy2 + u3), x7) + w[7 * B + i];
}

extern "C" void kernel_launch(void* const* d_in, const int* in_sizes, int n_in,
                              void* d_out, int out_size)
{
    const float* x    = (const float*)d_in[0];   // [8, B]
    const float* u    = (const float*)d_in[1];   // [4, B]
    const float* w    = (const float*)d_in[2];   // [8, B]
    const float* xbar = (const float*)d_in[3];   // [8]
    float* out = (float*)d_out;                  // [8, B]

    const int B = in_sizes[0] / 8;

    if ((B & 3) == 0) {
        const int n4 = B / 4;
        const int threads = 256;
        const int blocks = (n4 + threads - 1) / threads;
        tworobots_step<<<blocks, threads>>>((const float4*)x, (const float4*)u,
                                            (const float4*)w, xbar,
                                            (float4*)out, n4);
    } else {
        const int threads = 256;
        const int blocks = (B + threads - 1) / threads;
        tworobots_step_scalar<<<blocks, threads>>>(x, u, w, xbar, out, B);
    }
}

// round 2
// speedup vs baseline: 1.1349x; 1.1349x over previous
#include <cuda_runtime.h>

// TwoRobots Euler step — affine form (trig collapses: Fk*cos(atan2(dy,dx)) = KS*dx).
// R2: split into 4 independent (pos,vel,ctrl) pairs per column so each thread
// does only 5 float4 loads + 2 stores → front-batched MLP, 4x thread count.
//
// pair p -> rows: pos = p + 2*(p>>1)*... : {0,1,4,5}, vel = pos+2, ctrl row = p.
//   o_pos = pos + H*vel + w_pos
//   o_vel = vel + H*(-KS*(pos - xbar[pos_row]) - CD*vel + u) + w_vel

#define HSTEP 0.05f
#define KS    2.0f
#define CD    2.0f

__global__ __launch_bounds__(256)
void tworobots_pair(const float4* __restrict__ x,
                    const float4* __restrict__ u,
                    const float4* __restrict__ w,
                    const float*  __restrict__ xbar,
                    float4* __restrict__ out,
                    int n4)
{
    const int i = blockIdx.x * blockDim.x + threadIdx.x;
    if (i >= n4) return;

    const int pair = blockIdx.y;                 // 0..3
    const int pr   = pair + ((pair >> 1) << 1);  // 0,1,4,5
    const int vr   = pr + 2;                     // 2,3,6,7

    const float xb = __ldg(&xbar[pr]);

    // Front-batch all 5 loads (independent addresses -> 5 LDG.128 in flight).
    const float4 xp = x[pr * n4 + i];
    const float4 xv = x[vr * n4 + i];
    const float4 uu = u[pair * n4 + i];
    const float4 wp = w[pr * n4 + i];
    const float4 wv = w[vr * n4 + i];

    float4 op, ov;
#define LANE(c)                                                      \
    {                                                                \
        float fg = fmaf(-KS, (xp.c - xb), -CD * xv.c);               \
        op.c = fmaf(HSTEP, xv.c, xp.c) + wp.c;                       \
        ov.c = fmaf(HSTEP, (fg + uu.c), xv.c) + wv.c;                \
    }
    LANE(x) LANE(y) LANE(z) LANE(w)
#undef LANE

    out[pr * n4 + i] = op;
    out[vr * n4 + i] = ov;
}

// Scalar fallback (B % 4 != 0) — same pair decomposition.
__global__ __launch_bounds__(256)
void tworobots_pair_scalar(const float* __restrict__ x,
                           const float* __restrict__ u,
                           const float* __restrict__ w,
                           const float* __restrict__ xbar,
                           float* __restrict__ out,
                           int B)
{
    const int i = blockIdx.x * blockDim.x + threadIdx.x;
    if (i >= B) return;

    const int pair = blockIdx.y;
    const int pr   = pair + ((pair >> 1) << 1);
    const int vr   = pr + 2;

    const float xb = __ldg(&xbar[pr]);

    const float xp = x[pr * B + i];
    const float xv = x[vr * B + i];
    const float uu = u[pair * B + i];
    const float wp = w[pr * B + i];
    const float wv = w[vr * B + i];

    float fg = fmaf(-KS, (xp - xb), -CD * xv);
    out[pr * B + i] = fmaf(HSTEP, xv, xp) + wp;
    out[vr * B + i] = fmaf(HSTEP, (fg + uu), xv) + wv;
}

extern "C" void kernel_launch(void* const* d_in, const int* in_sizes, int n_in,
                              void* d_out, int out_size)
{
    const float* x    = (const float*)d_in[0];   // [8, B]
    const float* u    = (const float*)d_in[1];   // [4, B]
    const float* w    = (const float*)d_in[2];   // [8, B]
    const float* xbar = (const float*)d_in[3];   // [8]
    float* out = (float*)d_out;                  // [8, B]

    const int B = in_sizes[0] / 8;
    const int threads = 256;

    if ((B & 3) == 0) {
        const int n4 = B / 4;
        dim3 grid((n4 + threads - 1) / threads, 4);
        tworobots_pair<<<grid, threads>>>((const float4*)x, (const float4*)u,
                                          (const float4*)w, xbar,
                                          (float4*)out, n4);
    } else {
        dim3 grid((B + threads - 1) / threads, 4);
        tworobots_pair_scalar<<<grid, threads>>>(x, u, w, xbar, out, B);
    }
}